// round 14
// baseline (speedup 1.0000x reference)
#include <cuda_runtime.h>
#include <cuda_fp16.h>
#include <cstdint>

// out[dst[e]] += edge_attr[e] * x[src[e]],  D=64 f32, indices int32.
// History: R2 scatter 58us. R4/R6 bucket+gather 47.6us. R7 fp16 46.8us.
// R10 fused persistent (convert||fill, grid barrier, fp16 gather): 45.5us.
// R8/R9/R12/R13: four gather-inner-loop restructures all regressed/neutral
// -> the loop is pareto-optimal at fixed occupancy. R14: R10 verbatim but
// (a) launch_bounds(256,8) => regs<=32 => 64 warps/SM (+33% latency cover;
// grid sized from runtime occupancy query so the barrier can't deadlock),
// (b) convert shrunk to 1/8 of blocks (it's DRAM-bound ~4us; fill binds).

#define BUCKET_CAP 192           // Poisson(40) over 25K bins: max ~85
#define MAX_CB     32768
#define MAX_NODES  131072

__device__ int      g_counts[MAX_CB];                        // zero-init, self-resetting
__device__ int2     g_bucket[(size_t)MAX_CB * BUCKET_CAP];   // {src, attr bits}
__device__ uint2    g_xh[(size_t)MAX_NODES * 16];            // x as fp16: [node][32] half2
__device__ unsigned g_bar;                                   // monotonic barrier counter

// ---------------- helpers ----------------
__device__ __forceinline__ void _fill_one(int s, int d, float w,
                                          int n_coarse, int n_nodes) {
    if ((unsigned)d >= (unsigned)n_coarse) return;
    if ((unsigned)s >= (unsigned)n_nodes) { s = 0; w = 0.f; }
    int pos = atomicAdd(&g_counts[d], 1);
    if (pos < BUCKET_CAP)
        g_bucket[(unsigned)d * BUCKET_CAP + pos] = make_int2(s, __float_as_int(w));
    // overflow: true total stays in g_counts; gather rescans exactly.
}

__device__ __forceinline__ void _acc2(float2& acc, const __half2* __restrict__ xh2,
                                      unsigned s, float wt, unsigned lane) {
    float2 v = __half22float2(xh2[s * 32u + lane]);
    acc.x = fmaf(wt, v.x, acc.x);
    acc.y = fmaf(wt, v.y, acc.y);
}

// Replay-safe grid barrier: counter only ever increments; each call's blocks
// wait for the next multiple of gridDim.x. Requires all blocks resident
// (guaranteed: grid sized from the runtime occupancy query).
__device__ __forceinline__ void _grid_barrier(unsigned nB) {
    __threadfence();
    __syncthreads();
    if (threadIdx.x == 0) {
        unsigned arrive;
        asm volatile("atom.add.release.gpu.u32 %0, [%1], 1;"
                     : "=r"(arrive) : "l"(&g_bar) : "memory");
        arrive += 1;
        unsigned target = ((arrive - 1) / nB + 1) * nB;
        unsigned cur;
        do {
            asm volatile("ld.acquire.gpu.u32 %0, [%1];"
                         : "=r"(cur) : "l"(&g_bar) : "memory");
        } while (cur < target);
    }
    __syncthreads();
}

// ---------------- fused persistent kernel ----------------
__global__ void __launch_bounds__(256, 8)
_fused_kernel(const float4* __restrict__ x4,     // x as [n_nodes*16] float4
              const float2* __restrict__ x2,     // fp32 x (overflow path)
              const int* __restrict__ src, const int* __restrict__ dst,
              const float* __restrict__ attr,
              float2* __restrict__ out2,          // [n_coarse, 32] float2
              int num_edges, int n_coarse, int n_nodes, int vec_ok) {
    const unsigned nB  = gridDim.x;
    const unsigned bid = blockIdx.x;
    const unsigned tid = threadIdx.x;

    // ---- phase 1: convert (blocks [0, convB)) || fill (rest) ----
    const unsigned convB = (nB / 8 > 0) ? nB / 8 : 1;
    if (bid < convB) {
        int n16 = n_nodes * 16;
        for (int t = bid * 256 + tid; t < n16; t += convB * 256) {
            float4 v = x4[t];
            __half2 h0 = __floats2half2_rn(v.x, v.y);
            __half2 h1 = __floats2half2_rn(v.z, v.w);
            uint2 u;
            u.x = *(const unsigned*)&h0;
            u.y = *(const unsigned*)&h1;
            g_xh[t] = u;
        }
    } else {
        const unsigned fB = nB - convB;
        const unsigned fbid = bid - convB;
        int nchunks = (num_edges + 3) / 4;
        for (int ch = fbid * 256 + tid; ch < nchunks; ch += fB * 256) {
            int base = ch * 4;
            if (vec_ok && base + 4 <= num_edges) {
                int4   s4 = *(const int4*)(src + base);
                int4   d4 = *(const int4*)(dst + base);
                float4 w4 = *(const float4*)(attr + base);
                _fill_one(s4.x, d4.x, w4.x, n_coarse, n_nodes);
                _fill_one(s4.y, d4.y, w4.y, n_coarse, n_nodes);
                _fill_one(s4.z, d4.z, w4.z, n_coarse, n_nodes);
                _fill_one(s4.w, d4.w, w4.w, n_coarse, n_nodes);
            } else {
                int m = min(4, num_edges - base);
                for (int k = 0; k < m; k++) {
                    int e = base + k;
                    _fill_one(src[e], dst[e], attr[e], n_coarse, n_nodes);
                }
            }
        }
    }

    // ---- grid barrier: fill + convert complete ----
    _grid_barrier(nB);

    // ---- phase 2: gather, one warp per node (R10/R7 proven loop) ----
    const __half2* __restrict__ xh2 = (const __half2*)g_xh;
    unsigned lane   = tid & 31;
    unsigned gwarp  = bid * 8 + (tid >> 5);
    unsigned nwarps = nB * 8;

    for (int w = gwarp; w < n_coarse; w += nwarps) {
        int raw_cnt = g_counts[w];
        float2 acc = make_float2(0.f, 0.f);

        if (raw_cnt <= BUCKET_CAP) {
            const int2* __restrict__ b = g_bucket + (unsigned)w * BUCKET_CAP;
            int i = 0;
            for (; i + 4 <= raw_cnt; i += 4) {
                int2 p0 = b[i], p1 = b[i + 1], p2 = b[i + 2], p3 = b[i + 3];
                _acc2(acc, xh2, (unsigned)p0.x, __int_as_float(p0.y), lane);
                _acc2(acc, xh2, (unsigned)p1.x, __int_as_float(p1.y), lane);
                _acc2(acc, xh2, (unsigned)p2.x, __int_as_float(p2.y), lane);
                _acc2(acc, xh2, (unsigned)p3.x, __int_as_float(p3.y), lane);
            }
            for (; i < raw_cnt; i++) {
                int2 p = b[i];
                _acc2(acc, xh2, (unsigned)p.x, __int_as_float(p.y), lane);
            }
        } else {
            // overflow (statistically never): exact fp32 rescan
            for (int e = 0; e < num_edges; e++) {
                if (dst[e] == w) {
                    int s = src[e];
                    float wt = attr[e];
                    if ((unsigned)s >= (unsigned)n_nodes) { s = 0; wt = 0.f; }
                    float2 v = x2[(unsigned)s * 32u + lane];
                    acc.x = fmaf(wt, v.x, acc.x);
                    acc.y = fmaf(wt, v.y, acc.y);
                }
            }
        }

        out2[(unsigned)w * 32u + lane] = acc;
        if (lane == 0) g_counts[w] = 0;   // self-reset for next call
    }
}

// ---------- fallback (shapes exceed scratch): atomic scatter, fp32 ----------
__global__ void _zero_out_kernel(float4* __restrict__ out, int n4) {
    int i = blockIdx.x * blockDim.x + threadIdx.x;
    if (i < n4) out[i] = make_float4(0.f, 0.f, 0.f, 0.f);
}

__global__ void __launch_bounds__(256)
_scatter_add_kernel(const float4* __restrict__ x4,
                    const int* __restrict__ src,
                    const int* __restrict__ dst,
                    const float* __restrict__ attr,
                    float* __restrict__ out,
                    int num_edges, int n_nodes, int n_coarse) {
    int t = blockIdx.x * blockDim.x + threadIdx.x;
    int e = t >> 4;
    int c = t & 15;
    if (e >= num_edges) return;
    int s = src[e];
    int d = dst[e];
    float w = attr[e];
    if ((unsigned)s >= (unsigned)n_nodes || (unsigned)d >= (unsigned)n_coarse) return;
    float4 v = x4[(long long)s * 16 + c];
    v.x *= w; v.y *= w; v.z *= w; v.w *= w;
    float* p = out + (long long)d * 64 + c * 4;
    asm volatile("red.global.add.v4.f32 [%0], {%1, %2, %3, %4};"
                 :: "l"(p), "f"(v.x), "f"(v.y), "f"(v.z), "f"(v.w)
                 : "memory");
}

extern "C" void kernel_launch(void* const* d_in, const int* in_sizes, int n_in,
                              void* d_out, int out_size) {
    const float* x    = (const float*)d_in[0];     // [n_nodes, 64] f32
    const int*   eidx = (const int*)d_in[1];       // [2, E] int32
    const float* attr = (const float*)d_in[2];     // [E] f32
    float*       out  = (float*)d_out;             // [n_coarse, 64] f32

    int num_edges = in_sizes[2];
    int n_nodes   = in_sizes[0] / 64;
    int n_coarse  = out_size / 64;
    const int* src = eidx;
    const int* dst = eidx + num_edges;

    if (n_coarse <= MAX_CB && n_nodes <= MAX_NODES) {
        int vec_ok = ((num_edges & 3) == 0) &&
                     ((((unsigned long long)(uintptr_t)eidx) & 15ull) == 0) &&
                     ((((unsigned long long)(uintptr_t)attr) & 15ull) == 0);

        int sms = 148;
        cudaDeviceGetAttribute(&sms, cudaDevAttrMultiProcessorCount, 0);
        // Grid sized from ACTUAL achievable residency -> barrier is safe.
        int occB = 0;
        cudaOccupancyMaxActiveBlocksPerMultiprocessor(&occB, _fused_kernel, 256, 0);
        if (occB < 1) occB = 1;
        if (occB > 8) occB = 8;
        int nB = sms * occB;

        _fused_kernel<<<nB, 256>>>((const float4*)x, (const float2*)x,
                                   src, dst, attr, (float2*)out,
                                   num_edges, n_coarse, n_nodes, vec_ok);
    } else {
        int n4 = out_size / 4;
        _zero_out_kernel<<<(n4 + 255) / 256, 256>>>((float4*)out, n4);
        long long tt = (long long)num_edges * 16;
        _scatter_add_kernel<<<(int)((tt + 255) / 256), 256>>>(
            (const float4*)x, src, dst, attr, out, num_edges, n_nodes, n_coarse);
    }
}

// round 15
// speedup vs baseline: 1.2706x; 1.2706x over previous
#include <cuda_runtime.h>
#include <cuda_fp16.h>
#include <cstdint>

// out[dst[e]] += edge_attr[e] * x[src[e]],  D=64 f32, indices int32.
// History: R2 scatter 58us. R4/R6 bucket+gather 47.6us. R7 fp16 46.8us.
// R10 fused persistent (convert||fill 1/4-3/4, grid barrier, fp16 gather,
// lb(256,6)): 45.5us = best. R11 (fp32 gather), R12 (meta prefetch),
// R13 (x double-buffer), R14 (64 warps/SM) ALL regressed/neutral -> R10 is
// a confirmed local optimum; gather is L1tex-pipeline bound.
// R15: exact R10 revert + ONE isolated delta: bucket metadata read as int4
// (2 edges / 16B uniform load) instead of 4x int2. lb(256,6) caps regs at
// 42 so occupancy cannot drop.

#define BUCKET_CAP 192           // Poisson(40) over 25K bins: max ~85
#define MAX_CB     32768
#define MAX_NODES  131072

__device__ int      g_counts[MAX_CB];                        // zero-init, self-resetting
__device__ int2     g_bucket[(size_t)MAX_CB * BUCKET_CAP];   // {src, attr bits}
__device__ uint2    g_xh[(size_t)MAX_NODES * 16];            // x as fp16: [node][32] half2
__device__ unsigned g_bar;                                   // monotonic barrier counter

// ---------------- helpers ----------------
__device__ __forceinline__ void _fill_one(int s, int d, float w,
                                          int n_coarse, int n_nodes) {
    if ((unsigned)d >= (unsigned)n_coarse) return;
    if ((unsigned)s >= (unsigned)n_nodes) { s = 0; w = 0.f; }
    int pos = atomicAdd(&g_counts[d], 1);
    if (pos < BUCKET_CAP)
        g_bucket[(unsigned)d * BUCKET_CAP + pos] = make_int2(s, __float_as_int(w));
    // overflow: true total stays in g_counts; gather rescans exactly.
}

__device__ __forceinline__ void _acc2(float2& acc, const __half2* __restrict__ xh2,
                                      unsigned s, float wt, unsigned lane) {
    float2 v = __half22float2(xh2[s * 32u + lane]);
    acc.x = fmaf(wt, v.x, acc.x);
    acc.y = fmaf(wt, v.y, acc.y);
}

// Replay-safe grid barrier: counter only ever increments; each call's blocks
// wait for the next multiple of gridDim.x. Requires all blocks resident.
__device__ __forceinline__ void _grid_barrier(unsigned nB) {
    __threadfence();
    __syncthreads();
    if (threadIdx.x == 0) {
        unsigned arrive;
        asm volatile("atom.add.release.gpu.u32 %0, [%1], 1;"
                     : "=r"(arrive) : "l"(&g_bar) : "memory");
        arrive += 1;
        unsigned target = ((arrive - 1) / nB + 1) * nB;
        unsigned cur;
        do {
            asm volatile("ld.acquire.gpu.u32 %0, [%1];"
                         : "=r"(cur) : "l"(&g_bar) : "memory");
        } while (cur < target);
    }
    __syncthreads();
}

// ---------------- fused persistent kernel ----------------
__global__ void __launch_bounds__(256, 6)
_fused_kernel(const float4* __restrict__ x4,     // x as [n_nodes*16] float4
              const float2* __restrict__ x2,     // fp32 x (overflow path)
              const int* __restrict__ src, const int* __restrict__ dst,
              const float* __restrict__ attr,
              float2* __restrict__ out2,          // [n_coarse, 32] float2
              int num_edges, int n_coarse, int n_nodes, int vec_ok) {
    const unsigned nB  = gridDim.x;
    const unsigned bid = blockIdx.x;
    const unsigned tid = threadIdx.x;

    // ---- phase 1: convert (blocks [0, convB)) || fill (rest) ----
    const unsigned convB = nB / 4;
    if (bid < convB) {
        int n16 = n_nodes * 16;
        for (int t = bid * 256 + tid; t < n16; t += convB * 256) {
            float4 v = x4[t];
            __half2 h0 = __floats2half2_rn(v.x, v.y);
            __half2 h1 = __floats2half2_rn(v.z, v.w);
            uint2 u;
            u.x = *(const unsigned*)&h0;
            u.y = *(const unsigned*)&h1;
            g_xh[t] = u;
        }
    } else {
        const unsigned fB = nB - convB;
        const unsigned fbid = bid - convB;
        int nchunks = (num_edges + 3) / 4;
        for (int ch = fbid * 256 + tid; ch < nchunks; ch += fB * 256) {
            int base = ch * 4;
            if (vec_ok && base + 4 <= num_edges) {
                int4   s4 = *(const int4*)(src + base);
                int4   d4 = *(const int4*)(dst + base);
                float4 w4 = *(const float4*)(attr + base);
                _fill_one(s4.x, d4.x, w4.x, n_coarse, n_nodes);
                _fill_one(s4.y, d4.y, w4.y, n_coarse, n_nodes);
                _fill_one(s4.z, d4.z, w4.z, n_coarse, n_nodes);
                _fill_one(s4.w, d4.w, w4.w, n_coarse, n_nodes);
            } else {
                int m = min(4, num_edges - base);
                for (int k = 0; k < m; k++) {
                    int e = base + k;
                    _fill_one(src[e], dst[e], attr[e], n_coarse, n_nodes);
                }
            }
        }
    }

    // ---- grid barrier: fill + convert complete ----
    _grid_barrier(nB);

    // ---- phase 2: gather, one warp per node (R10 loop, int4 metadata) ----
    const __half2* __restrict__ xh2 = (const __half2*)g_xh;
    unsigned lane   = tid & 31;
    unsigned gwarp  = bid * 8 + (tid >> 5);
    unsigned nwarps = nB * 8;

    for (int w = gwarp; w < n_coarse; w += nwarps) {
        int raw_cnt = g_counts[w];
        float2 acc = make_float2(0.f, 0.f);

        if (raw_cnt <= BUCKET_CAP) {
            const int2* __restrict__ b = g_bucket + (unsigned)w * BUCKET_CAP;
            int i = 0;
            for (; i + 4 <= raw_cnt; i += 4) {
                // 2 uniform LDG.128 for 4 edges' metadata
                int4 ma = *(const int4*)(b + i);       // {s0,w0, s1,w1}
                int4 mb = *(const int4*)(b + i + 2);   // {s2,w2, s3,w3}
                _acc2(acc, xh2, (unsigned)ma.x, __int_as_float(ma.y), lane);
                _acc2(acc, xh2, (unsigned)ma.z, __int_as_float(ma.w), lane);
                _acc2(acc, xh2, (unsigned)mb.x, __int_as_float(mb.y), lane);
                _acc2(acc, xh2, (unsigned)mb.z, __int_as_float(mb.w), lane);
            }
            for (; i < raw_cnt; i++) {
                int2 p = b[i];
                _acc2(acc, xh2, (unsigned)p.x, __int_as_float(p.y), lane);
            }
        } else {
            // overflow (statistically never): exact fp32 rescan
            for (int e = 0; e < num_edges; e++) {
                if (dst[e] == w) {
                    int s = src[e];
                    float wt = attr[e];
                    if ((unsigned)s >= (unsigned)n_nodes) { s = 0; wt = 0.f; }
                    float2 v = x2[(unsigned)s * 32u + lane];
                    acc.x = fmaf(wt, v.x, acc.x);
                    acc.y = fmaf(wt, v.y, acc.y);
                }
            }
        }

        out2[(unsigned)w * 32u + lane] = acc;
        if (lane == 0) g_counts[w] = 0;   // self-reset for next call
    }
}

// ---------- fallback (shapes exceed scratch): atomic scatter, fp32 ----------
__global__ void _zero_out_kernel(float4* __restrict__ out, int n4) {
    int i = blockIdx.x * blockDim.x + threadIdx.x;
    if (i < n4) out[i] = make_float4(0.f, 0.f, 0.f, 0.f);
}

__global__ void __launch_bounds__(256)
_scatter_add_kernel(const float4* __restrict__ x4,
                    const int* __restrict__ src,
                    const int* __restrict__ dst,
                    const float* __restrict__ attr,
                    float* __restrict__ out,
                    int num_edges, int n_nodes, int n_coarse) {
    int t = blockIdx.x * blockDim.x + threadIdx.x;
    int e = t >> 4;
    int c = t & 15;
    if (e >= num_edges) return;
    int s = src[e];
    int d = dst[e];
    float w = attr[e];
    if ((unsigned)s >= (unsigned)n_nodes || (unsigned)d >= (unsigned)n_coarse) return;
    float4 v = x4[(long long)s * 16 + c];
    v.x *= w; v.y *= w; v.z *= w; v.w *= w;
    float* p = out + (long long)d * 64 + c * 4;
    asm volatile("red.global.add.v4.f32 [%0], {%1, %2, %3, %4};"
                 :: "l"(p), "f"(v.x), "f"(v.y), "f"(v.z), "f"(v.w)
                 : "memory");
}

extern "C" void kernel_launch(void* const* d_in, const int* in_sizes, int n_in,
                              void* d_out, int out_size) {
    const float* x    = (const float*)d_in[0];     // [n_nodes, 64] f32
    const int*   eidx = (const int*)d_in[1];       // [2, E] int32
    const float* attr = (const float*)d_in[2];     // [E] f32
    float*       out  = (float*)d_out;             // [n_coarse, 64] f32

    int num_edges = in_sizes[2];
    int n_nodes   = in_sizes[0] / 64;
    int n_coarse  = out_size / 64;
    const int* src = eidx;
    const int* dst = eidx + num_edges;

    if (n_coarse <= MAX_CB && n_nodes <= MAX_NODES) {
        int vec_ok = ((num_edges & 3) == 0) &&
                     ((((unsigned long long)(uintptr_t)eidx) & 15ull) == 0) &&
                     ((((unsigned long long)(uintptr_t)attr) & 15ull) == 0);

        int sms = 148;
        cudaDeviceGetAttribute(&sms, cudaDevAttrMultiProcessorCount, 0);
        int nB = sms * 6;       // launch_bounds(256,6) guarantees residency

        _fused_kernel<<<nB, 256>>>((const float4*)x, (const float2*)x,
                                   src, dst, attr, (float2*)out,
                                   num_edges, n_coarse, n_nodes, vec_ok);
    } else {
        int n4 = out_size / 4;
        _zero_out_kernel<<<(n4 + 255) / 256, 256>>>((float4*)out, n4);
        long long tt = (long long)num_edges * 16;
        _scatter_add_kernel<<<(int)((tt + 255) / 256), 256>>>(
            (const float4*)x, src, dst, attr, out, num_edges, n_nodes, n_coarse);
    }
}